// round 5
// baseline (speedup 1.0000x reference)
#include <cuda_runtime.h>
#include <math.h>

#define Bz   128
#define Hh   512
#define G4   2048
#define Tt   256
#define INZ  64
#define OUTL 512
#define NBLK 128

typedef unsigned long long u64;

// ---------------- device scratch ----------------
__device__ float g_xpe[(size_t)Tt * Bz * G4];   // [t][b][4H]
__device__ float g_xpd[(size_t)Tt * Bz * G4];
__device__ float g_hse[(size_t)Tt * Hh * Bz];   // [t][h][b]
__device__ float g_hsd[(size_t)Tt * Hh * Bz];
__device__ float g_hA[Hh * Bz];
__device__ float g_hB[Hh * Bz];
__device__ float g_h2A[Hh * Bz];
__device__ float g_h2B[Hh * Bz];
__device__ float g_fcp[(size_t)Tt * Bz * OUTL];
__device__ unsigned g_ck[8];    // [layer][chunk] monotonic producer counters

// ---------------- f32x2 helpers ----------------
__device__ __forceinline__ u64 pack2(float lo, float hi) {
    u64 r; asm("mov.b64 %0,{%1,%2};" : "=l"(r) : "f"(lo), "f"(hi)); return r;
}
__device__ __forceinline__ void unpack2(u64 v, float& lo, float& hi) {
    asm("mov.b64 {%0,%1},%2;" : "=f"(lo), "=f"(hi) : "l"(v));
}
__device__ __forceinline__ u64 fma2(u64 a, u64 b, u64 c) {
    u64 d; asm("fma.rn.f32x2 %0,%1,%2,%3;" : "=l"(d) : "l"(a), "l"(b), "l"(c)); return d;
}
__device__ __forceinline__ u64 add2(u64 a, u64 b) {
    u64 d; asm("add.rn.f32x2 %0,%1,%2;" : "=l"(d) : "l"(a), "l"(b)); return d;
}
__device__ __forceinline__ float fsig(float x) { return __fdividef(1.f, 1.f + __expf(-x)); }
__device__ __forceinline__ float ftanh_(float x) { return 2.f * fsig(2.f * x) - 1.f; }
__device__ __forceinline__ unsigned ld_acq(const unsigned* p) {
    unsigned v; asm volatile("ld.acquire.gpu.u32 %0,[%1];" : "=r"(v) : "l"(p) : "memory"); return v;
}
__device__ __forceinline__ void red_rel_add(unsigned* p, unsigned v) {
    asm volatile("red.release.gpu.global.add.u32 [%0],%1;" :: "l"(p), "r"(v) : "memory");
}
__device__ __forceinline__ void poll_ge(const unsigned* p, unsigned target) {
    while (ld_acq(p) < target) {}
}

// ---------------- init ----------------
__global__ void init_h(const float* __restrict__ h0e, const float* __restrict__ h0d) {
    int i = blockIdx.x * blockDim.x + threadIdx.x;
    if (i < Hh * Bz) {
        int k = i >> 7, b = i & 127;
        g_hA[i]  = h0e[b * Hh + k];
        g_h2A[i] = h0d[b * Hh + k];
    }
}
__global__ void init_bar() {
    if (threadIdx.x < 8) g_ck[threadIdx.x] = 0u;
}

// ---------------- input projection GEMM (f32x2) ----------------
template <int MODE>
__global__ void __launch_bounds__(256)
inproj_gemm(const float* __restrict__ A_or_x, const float* __restrict__ W,
            const float* __restrict__ b0v, const float* __restrict__ b1v,
            float* __restrict__ out, int K) {
    __shared__ __align__(16) float As[8][128];
    __shared__ __align__(16) float Bs[8][128];

    const int m0  = blockIdx.y * 128;
    const int n0  = blockIdx.x * 128;
    const int tid = threadIdx.x;
    const int txx = tid & 15;
    const int tyy = tid >> 4;
    const int lrow = tid >> 1;
    const int lkq  = (tid & 1) * 4;
    const int arow = tid >> 5;
    const int acol = (tid & 31) * 4;

    u64 acc[8][4];
#pragma unroll
    for (int i = 0; i < 8; i++)
#pragma unroll
        for (int j = 0; j < 4; j++) acc[i][j] = 0ull;

    float4 aPf, bPf;
    float  aPfS[4];

    if (MODE == 1) {
        aPf = *reinterpret_cast<const float4*>(
            &A_or_x[(size_t)blockIdx.y * Hh * Bz + (size_t)arow * Bz + acol]);
    } else {
        int m = m0 + lrow;
        int tt = m >> 7, b = m & 127;
#pragma unroll
        for (int i = 0; i < 4; i++)
            aPfS[i] = A_or_x[(size_t)b * (INZ * Tt) + (size_t)(lkq + i) * Tt + tt];
    }
    bPf = *reinterpret_cast<const float4*>(&W[(size_t)(n0 + lrow) * K + lkq]);

    for (int k0 = 0; k0 < K; k0 += 8) {
        if (MODE == 1) {
            *reinterpret_cast<float4*>(&As[arow][acol]) = aPf;
        } else {
#pragma unroll
            for (int i = 0; i < 4; i++) As[lkq + i][lrow] = aPfS[i];
        }
        Bs[lkq + 0][lrow] = bPf.x; Bs[lkq + 1][lrow] = bPf.y;
        Bs[lkq + 2][lrow] = bPf.z; Bs[lkq + 3][lrow] = bPf.w;
        __syncthreads();

        int kn = k0 + 8;
        if (kn < K) {
            if (MODE == 1) {
                aPf = *reinterpret_cast<const float4*>(
                    &A_or_x[(size_t)blockIdx.y * Hh * Bz + (size_t)(kn + arow) * Bz + acol]);
            } else {
                int m = m0 + lrow;
                int tt = m >> 7, b = m & 127;
#pragma unroll
                for (int i = 0; i < 4; i++)
                    aPfS[i] = A_or_x[(size_t)b * (INZ * Tt) + (size_t)(kn + lkq + i) * Tt + tt];
            }
            bPf = *reinterpret_cast<const float4*>(&W[(size_t)(n0 + lrow) * K + kn + lkq]);
        }

#pragma unroll
        for (int kk = 0; kk < 8; kk++) {
            float a[8];
            *reinterpret_cast<float4*>(&a[0]) = *reinterpret_cast<const float4*>(&As[kk][tyy * 8]);
            *reinterpret_cast<float4*>(&a[4]) = *reinterpret_cast<const float4*>(&As[kk][tyy * 8 + 4]);
            ulonglong2 bp01 = *reinterpret_cast<const ulonglong2*>(&Bs[kk][txx * 8]);
            ulonglong2 bp23 = *reinterpret_cast<const ulonglong2*>(&Bs[kk][txx * 8 + 4]);
            u64 bp[4] = {bp01.x, bp01.y, bp23.x, bp23.y};
#pragma unroll
            for (int i = 0; i < 8; i++) {
                u64 as = pack2(a[i], a[i]);
#pragma unroll
                for (int j = 0; j < 4; j++)
                    acc[i][j] = fma2(as, bp[j], acc[i][j]);
            }
        }
        __syncthreads();
    }

#pragma unroll
    for (int i = 0; i < 8; i++) {
        int m = m0 + tyy * 8 + i;
#pragma unroll
        for (int j = 0; j < 4; j++) {
            int n = n0 + txx * 8 + 2 * j;
            float lo, hi; unpack2(acc[i][j], lo, hi);
            float2 v = make_float2(lo + b0v[n] + b1v[n], hi + b0v[n + 1] + b1v[n + 1]);
            *reinterpret_cast<float2*>(&out[(size_t)m * G4 + n]) = v;
        }
    }
}

// ---------------- persistent LSTM, dataflow-synced ----------------
// 128 blocks x 512 threads. Block owns 4 hidx x 4 gates (16 weight rows,
// pre-splatted f32x2 in SMEM). 4 chunks of 128 k-rows, double-buffered
// cp.async. Per-chunk producer counters replace the grid barrier:
// chunk c produced by blocks [32c, 32c+32); counter[c] == 32*(t+1) when
// version t+1 of chunk c is published.
__global__ void __launch_bounds__(512, 1)
lstm_persistent(const float* __restrict__ xp_all,   // [t][b][2048]
                const float* __restrict__ whh,      // [2048][512]
                const float* __restrict__ c0,       // [b][512]
                float* __restrict__ hbuf0,          // [512][128]  version even
                float* __restrict__ hbuf1,          //             version odd
                float* __restrict__ hs_t,           // [t][512][128]
                int layer) {
    extern __shared__ char sm_[];
    u64*   ws2 = (u64*)sm_;                               // [512][16] splats, 64KB
    float* hb  = (float*)(sm_ + 65536);                   // [2][128][128] 128KB
    u64*   red = (u64*)(sm_ + 65536 + 131072);            // [3][128][8] 24KB
    float* xs  = (float*)(sm_ + 65536 + 131072 + 24576);  // [512][4] 8KB
    float* cst = (float*)(sm_ + 65536 + 131072 + 24576 + 8192);  // [4][128] 2KB

    const int tid   = threadIdx.x;
    const int g     = tid >> 7;          // k-group 0..3
    const int tid7  = tid & 127;
    const int hh    = tid7 & 3;
    const int bq    = tid7 >> 2;
    const int hidx0 = blockIdx.x * 4;
    const int myGrp = blockIdx.x >> 5;   // which chunk this block produces

    unsigned* ck = &g_ck[layer * 4];

    // one-time weight load, pre-splatted: ws2[k][wh*4+q] = (w,w)
    for (int r = tid; r < 512 * 16; r += 512) {
        int k = r >> 4, idx = r & 15;
        int wh = idx >> 2, q = idx & 3;
        float w = whh[(size_t)(q * Hh + hidx0 + wh) * Hh + k];
        ws2[r] = pack2(w, w);
    }
    if (tid < 128) {
#pragma unroll
        for (int j = 0; j < 4; j++)
            cst[hh * 128 + bq * 4 + j] = c0[(size_t)(bq * 4 + j) * Hh + hidx0 + hh];
    }
    __syncthreads();

    const unsigned hb_s = (unsigned)__cvta_generic_to_shared(hb);

    // preamble: version 0 is ready; issue chunk 0 of t=0 into slot 0
    {
        unsigned sa = hb_s + tid * 16;
        const char* gp = (const char*)hbuf0 + tid * 16;
#pragma unroll
        for (int i = 0; i < 8; i++)
            asm volatile("cp.async.cg.shared.global [%0], [%1], 16;"
                         :: "r"(sa + i * 8192), "l"(gp + i * 8192));
        asm volatile("cp.async.commit_group;" ::: "memory");
    }

    // xp prefetch for t=0 (xs index = tid = b*4+q)
    float4 xr = *reinterpret_cast<const float4*>(
        &xp_all[(size_t)(tid >> 2) * G4 + (tid & 3) * Hh + hidx0]);

    for (int t = 0; t < Tt; t++) {
        const float* hp = (t & 1) ? hbuf1 : hbuf0;
        float*       hn = (t & 1) ? hbuf0 : hbuf1;

        u64 acc[8];
#pragma unroll
        for (int j = 0; j < 8; j++) acc[j] = 0ull;

#pragma unroll
        for (int c = 0; c < 4; c++) {
            asm volatile("cp.async.wait_group 0;" ::: "memory");
            __syncthreads();

            if (c < 3) {
                poll_ge(&ck[c + 1], 32u * (unsigned)t);
                unsigned sa = hb_s + ((c + 1) & 1) * 65536 + tid * 16;
                const char* gp = (const char*)(hp + (c + 1) * 16384) + tid * 16;
#pragma unroll
                for (int i = 0; i < 8; i++)
                    asm volatile("cp.async.cg.shared.global [%0], [%1], 16;"
                                 :: "r"(sa + i * 8192), "l"(gp + i * 8192));
                asm volatile("cp.async.commit_group;" ::: "memory");
            } else if (t + 1 < Tt && myGrp != 0) {
                // issue chunk 0 of next step (producers are blocks 0..31)
                poll_ge(&ck[0], 32u * (unsigned)(t + 1));
                unsigned sa = hb_s + tid * 16;
                const char* gp = (const char*)hn + tid * 16;
#pragma unroll
                for (int i = 0; i < 8; i++)
                    asm volatile("cp.async.cg.shared.global [%0], [%1], 16;"
                                 :: "r"(sa + i * 8192), "l"(gp + i * 8192));
                asm volatile("cp.async.commit_group;" ::: "memory");
            }

            const float* bufk = hb + (c & 1) * 16384 + (size_t)(g * 32) * 128 + bq * 4;
            const u64*   wk   = ws2 + (size_t)(c * 128 + g * 32) * 16 + hh * 4;
#pragma unroll 8
            for (int kk = 0; kk < 32; kk++) {
                ulonglong2 hpair = *reinterpret_cast<const ulonglong2*>(bufk + (size_t)kk * 128);
                ulonglong2 w01 = *reinterpret_cast<const ulonglong2*>(wk + (size_t)kk * 16);
                ulonglong2 w23 = *reinterpret_cast<const ulonglong2*>(wk + (size_t)kk * 16 + 2);
                acc[0] = fma2(hpair.x, w01.x, acc[0]);
                acc[4] = fma2(hpair.y, w01.x, acc[4]);
                acc[1] = fma2(hpair.x, w01.y, acc[1]);
                acc[5] = fma2(hpair.y, w01.y, acc[5]);
                acc[2] = fma2(hpair.x, w23.x, acc[2]);
                acc[6] = fma2(hpair.y, w23.x, acc[6]);
                acc[3] = fma2(hpair.x, w23.y, acc[3]);
                acc[7] = fma2(hpair.y, w23.y, acc[7]);
            }
        }

        // stage xp + partials
        *reinterpret_cast<float4*>(&xs[tid * 4]) = xr;
        if (g != 0) {
            u64* r = red + (size_t)(g - 1) * 1024 + tid7 * 8;
#pragma unroll
            for (int j = 0; j < 8; j++) r[j] = acc[j];
        }
        __syncthreads();

        if (g == 0) {
            float gate[4][4];   // [q][j]
#pragma unroll
            for (int p = 0; p < 2; p++)
#pragma unroll
                for (int q = 0; q < 4; q++) {
                    u64 s = acc[p * 4 + q];
                    s = add2(s, red[0 * 1024 + tid7 * 8 + p * 4 + q]);
                    s = add2(s, red[1 * 1024 + tid7 * 8 + p * 4 + q]);
                    s = add2(s, red[2 * 1024 + tid7 * 8 + p * 4 + q]);
                    unpack2(s, gate[q][p * 2 + 0], gate[q][p * 2 + 1]);
                }
            float hv[4];
#pragma unroll
            for (int j = 0; j < 4; j++) {
                int b = bq * 4 + j;
                float gi = gate[0][j] + xs[b * 16 + 0 + hh];
                float gf = gate[1][j] + xs[b * 16 + 4 + hh];
                float gg = gate[2][j] + xs[b * 16 + 8 + hh];
                float go = gate[3][j] + xs[b * 16 + 12 + hh];
                float cc = fsig(gf) * cst[hh * 128 + b] + fsig(gi) * ftanh_(gg);
                cst[hh * 128 + b] = cc;
                hv[j] = fsig(go) * ftanh_(cc);
            }
            float4 h4 = make_float4(hv[0], hv[1], hv[2], hv[3]);
            int off = (hidx0 + hh) * 128 + bq * 4;
            *reinterpret_cast<float4*>(&hn[off]) = h4;
            *reinterpret_cast<float4*>(&hs_t[(size_t)t * Hh * Bz + off]) = h4;
        }

        // prefetch next step's xp (independent of h)
        if (t + 1 < Tt)
            xr = *reinterpret_cast<const float4*>(
                &xp_all[(size_t)(t + 1) * Bz * G4 +
                        (size_t)(tid >> 2) * G4 + (tid & 3) * Hh + hidx0]);

        // publish this block's h slice
        __threadfence();
        __syncthreads();
        if (tid == 0) red_rel_add(&ck[myGrp], 1u);

        // group-0 blocks issue chunk 0 of next step AFTER signaling (self-dependency)
        if (t + 1 < Tt && myGrp == 0) {
            poll_ge(&ck[0], 32u * (unsigned)(t + 1));
            unsigned sa = hb_s + tid * 16;
            const char* gp = (const char*)hn + tid * 16;
#pragma unroll
            for (int i = 0; i < 8; i++)
                asm volatile("cp.async.cg.shared.global [%0], [%1], 16;"
                             :: "r"(sa + i * 8192), "l"(gp + i * 8192));
            asm volatile("cp.async.commit_group;" ::: "memory");
        }
    }
}

// ---------------- encoder output transpose: out[b][h][t] = hse_t[t][h][b] ----------------
__global__ void __launch_bounds__(256)
enc_transpose(const float* __restrict__ hs_t, float* __restrict__ out) {
    __shared__ float tile[32][33];
    int t0 = blockIdx.x * 32, b0 = blockIdx.y * 32, h = blockIdx.z;
    int tx = threadIdx.x & 31, ty = threadIdx.x >> 5;
#pragma unroll
    for (int i = ty; i < 32; i += 8)
        tile[i][tx] = hs_t[(size_t)(t0 + i) * (Hh * Bz) + (size_t)h * Bz + b0 + tx];
    __syncthreads();
#pragma unroll
    for (int i = ty; i < 32; i += 8)
        out[(size_t)(b0 + i) * (Hh * Tt) + (size_t)h * Tt + t0 + tx] = tile[tx][i];
}

// ---------------- FC partial GEMM (f32x2, k-split over t) ----------------
__global__ void __launch_bounds__(256)
fc_partial(const float* __restrict__ hsd_t, const float* __restrict__ Wfc) {
    const int t  = blockIdx.y;
    const int o0 = blockIdx.x * 128;
    const int tid = threadIdx.x;
    const int txx = tid & 15;
    const int tyy = tid >> 4;
    const int lrow = tid >> 1;
    const int lkq  = (tid & 1) * 4;
    const int arow = tid >> 5;
    const int acol = (tid & 31) * 4;

    __shared__ __align__(16) float As[8][128];
    __shared__ __align__(16) float Bs[8][128];

    u64 acc[8][4];
#pragma unroll
    for (int i = 0; i < 8; i++)
#pragma unroll
        for (int j = 0; j < 4; j++) acc[i][j] = 0ull;

    const float* Abase = hsd_t + (size_t)t * (Hh * Bz);

    for (int h0 = 0; h0 < Hh; h0 += 8) {
        *reinterpret_cast<float4*>(&As[arow][acol]) =
            *reinterpret_cast<const float4*>(&Abase[(size_t)(h0 + arow) * Bz + acol]);
#pragma unroll
        for (int i = 0; i < 4; i++)
            Bs[lkq + i][lrow] = Wfc[(size_t)(o0 + lrow) * (Hh * Tt) + (size_t)(h0 + lkq + i) * Tt + t];
        __syncthreads();
#pragma unroll
        for (int kk = 0; kk < 8; kk++) {
            float a[8];
            *reinterpret_cast<float4*>(&a[0]) = *reinterpret_cast<const float4*>(&As[kk][tyy * 8]);
            *reinterpret_cast<float4*>(&a[4]) = *reinterpret_cast<const float4*>(&As[kk][tyy * 8 + 4]);
            ulonglong2 bp01 = *reinterpret_cast<const ulonglong2*>(&Bs[kk][txx * 8]);
            ulonglong2 bp23 = *reinterpret_cast<const ulonglong2*>(&Bs[kk][txx * 8 + 4]);
            u64 bp[4] = {bp01.x, bp01.y, bp23.x, bp23.y};
#pragma unroll
            for (int i = 0; i < 8; i++) {
                u64 as = pack2(a[i], a[i]);
#pragma unroll
                for (int j = 0; j < 4; j++)
                    acc[i][j] = fma2(as, bp[j], acc[i][j]);
            }
        }
        __syncthreads();
    }

    float* part = g_fcp + (size_t)t * (Bz * OUTL);
#pragma unroll
    for (int i = 0; i < 8; i++) {
        int b = tyy * 8 + i;
#pragma unroll
        for (int j = 0; j < 4; j++) {
            float lo, hi; unpack2(acc[i][j], lo, hi);
            *reinterpret_cast<float2*>(&part[(size_t)b * OUTL + o0 + txx * 8 + 2 * j]) =
                make_float2(lo, hi);
        }
    }
}

__global__ void fc_reduce(const float* __restrict__ bfc, float* __restrict__ decoded) {
    int i = blockIdx.x * blockDim.x + threadIdx.x;
    if (i >= Bz * OUTL) return;
    float s = bfc[i & (OUTL - 1)];
    for (int t = 0; t < Tt; t++) s += g_fcp[(size_t)t * (Bz * OUTL) + i];
    decoded[i] = s;
}

// ---------------- launch ----------------
extern "C" void kernel_launch(void* const* d_in, const int* in_sizes, int n_in,
                              void* d_out, int out_size) {
    const float* x     = (const float*)d_in[0];
    const float* h0e   = (const float*)d_in[1];
    const float* c0e   = (const float*)d_in[2];
    const float* Wih_e = (const float*)d_in[3];
    const float* Whh_e = (const float*)d_in[4];
    const float* bih_e = (const float*)d_in[5];
    const float* bhh_e = (const float*)d_in[6];
    const float* h0d   = (const float*)d_in[7];
    const float* c0d   = (const float*)d_in[8];
    const float* Wih_d = (const float*)d_in[9];
    const float* Whh_d = (const float*)d_in[10];
    const float* bih_d = (const float*)d_in[11];
    const float* bhh_d = (const float*)d_in[12];
    const float* Wfc   = (const float*)d_in[13];
    const float* bfc   = (const float*)d_in[14];

    float* out = (float*)d_out;
    float* enc_out = out;
    float* decoded = out + (size_t)Bz * Hh * Tt;

    float *xpe, *xpd, *hse, *hsd, *hA, *hB, *h2A, *h2B;
    cudaGetSymbolAddress((void**)&xpe, g_xpe);
    cudaGetSymbolAddress((void**)&xpd, g_xpd);
    cudaGetSymbolAddress((void**)&hse, g_hse);
    cudaGetSymbolAddress((void**)&hsd, g_hsd);
    cudaGetSymbolAddress((void**)&hA,  g_hA);
    cudaGetSymbolAddress((void**)&hB,  g_hB);
    cudaGetSymbolAddress((void**)&h2A, g_h2A);
    cudaGetSymbolAddress((void**)&h2B, g_h2B);

    const int SMEM = 65536 + 131072 + 24576 + 8192 + 2048;   // 231424
    cudaFuncSetAttribute(lstm_persistent, cudaFuncAttributeMaxDynamicSharedMemorySize, SMEM);

    init_h<<<(Hh * Bz + 255) / 256, 256>>>(h0e, h0d);
    init_bar<<<1, 32>>>();

    inproj_gemm<0><<<dim3(16, 256), 256>>>(x, Wih_e, bih_e, bhh_e, xpe, INZ);

    lstm_persistent<<<NBLK, 512, SMEM>>>(xpe, Whh_e, c0e, hA, hB, hse, 0);

    inproj_gemm<1><<<dim3(16, 256), 256>>>(hse, Wih_d, bih_d, bhh_d, xpd, Hh);

    lstm_persistent<<<NBLK, 512, SMEM>>>(xpd, Whh_d, c0d, h2A, h2B, hsd, 1);

    enc_transpose<<<dim3(Tt / 32, Bz / 32, Hh), 256>>>(hse, enc_out);

    fc_partial<<<dim3(4, Tt), 256>>>(hsd, Wfc);
    fc_reduce<<<(Bz * OUTL + 255) / 256, 256>>>(bfc, decoded);
}

// round 6
// speedup vs baseline: 1.4391x; 1.4391x over previous
#include <cuda_runtime.h>
#include <math.h>

#define Bz   128
#define Hh   512
#define G4   2048
#define Tt   256
#define INZ  64
#define OUTL 512
#define NBLK 128

typedef unsigned long long u64;

// ---------------- device scratch ----------------
__device__ float g_xpe[(size_t)Tt * Bz * G4];   // [t][b][4H]
__device__ float g_xpd[(size_t)Tt * Bz * G4];
__device__ float g_hse[(size_t)Tt * Hh * Bz];   // [t][h][b]
__device__ float g_hsd[(size_t)Tt * Hh * Bz];
__device__ float g_hA[Hh * Bz];
__device__ float g_hB[Hh * Bz];
__device__ float g_h2A[Hh * Bz];
__device__ float g_h2B[Hh * Bz];
__device__ float g_fcp[(size_t)Tt * Bz * OUTL];
__device__ unsigned g_barCnt[2];

// ---------------- f32x2 helpers ----------------
__device__ __forceinline__ u64 pack2(float lo, float hi) {
    u64 r; asm("mov.b64 %0,{%1,%2};" : "=l"(r) : "f"(lo), "f"(hi)); return r;
}
__device__ __forceinline__ void unpack2(u64 v, float& lo, float& hi) {
    asm("mov.b64 {%0,%1},%2;" : "=f"(lo), "=f"(hi) : "l"(v));
}
__device__ __forceinline__ u64 fma2(u64 a, u64 b, u64 c) {
    u64 d; asm("fma.rn.f32x2 %0,%1,%2,%3;" : "=l"(d) : "l"(a), "l"(b), "l"(c)); return d;
}
__device__ __forceinline__ u64 add2(u64 a, u64 b) {
    u64 d; asm("add.rn.f32x2 %0,%1,%2;" : "=l"(d) : "l"(a), "l"(b)); return d;
}
__device__ __forceinline__ float fsig(float x) { return __fdividef(1.f, 1.f + __expf(-x)); }
__device__ __forceinline__ float ftanh_(float x) { return 2.f * fsig(2.f * x) - 1.f; }
__device__ __forceinline__ unsigned ld_acq(const unsigned* p) {
    unsigned v; asm volatile("ld.acquire.gpu.u32 %0,[%1];" : "=r"(v) : "l"(p) : "memory"); return v;
}
__device__ __forceinline__ void red_rel_add(unsigned* p, unsigned v) {
    asm volatile("red.release.gpu.global.add.u32 [%0],%1;" :: "l"(p), "r"(v) : "memory");
}

// ---------------- init ----------------
__global__ void init_h(const float* __restrict__ h0e, const float* __restrict__ h0d) {
    int i = blockIdx.x * blockDim.x + threadIdx.x;
    if (i < Hh * Bz) {
        int k = i >> 7, b = i & 127;
        g_hA[i]  = h0e[b * Hh + k];
        g_h2A[i] = h0d[b * Hh + k];
    }
}
__global__ void init_bar() {
    if (threadIdx.x < 2) g_barCnt[threadIdx.x] = 0u;
}

// ---------------- input projection GEMM (f32x2) ----------------
template <int MODE>
__global__ void __launch_bounds__(256)
inproj_gemm(const float* __restrict__ A_or_x, const float* __restrict__ W,
            const float* __restrict__ b0v, const float* __restrict__ b1v,
            float* __restrict__ out, int K) {
    __shared__ __align__(16) float As[8][128];
    __shared__ __align__(16) float Bs[8][128];

    const int m0  = blockIdx.y * 128;
    const int n0  = blockIdx.x * 128;
    const int tid = threadIdx.x;
    const int txx = tid & 15;
    const int tyy = tid >> 4;
    const int lrow = tid >> 1;
    const int lkq  = (tid & 1) * 4;
    const int arow = tid >> 5;
    const int acol = (tid & 31) * 4;

    u64 acc[8][4];
#pragma unroll
    for (int i = 0; i < 8; i++)
#pragma unroll
        for (int j = 0; j < 4; j++) acc[i][j] = 0ull;

    float4 aPf, bPf;
    float  aPfS[4];

    if (MODE == 1) {
        aPf = *reinterpret_cast<const float4*>(
            &A_or_x[(size_t)blockIdx.y * Hh * Bz + (size_t)arow * Bz + acol]);
    } else {
        int m = m0 + lrow;
        int tt = m >> 7, b = m & 127;
#pragma unroll
        for (int i = 0; i < 4; i++)
            aPfS[i] = A_or_x[(size_t)b * (INZ * Tt) + (size_t)(lkq + i) * Tt + tt];
    }
    bPf = *reinterpret_cast<const float4*>(&W[(size_t)(n0 + lrow) * K + lkq]);

    for (int k0 = 0; k0 < K; k0 += 8) {
        if (MODE == 1) {
            *reinterpret_cast<float4*>(&As[arow][acol]) = aPf;
        } else {
#pragma unroll
            for (int i = 0; i < 4; i++) As[lkq + i][lrow] = aPfS[i];
        }
        Bs[lkq + 0][lrow] = bPf.x; Bs[lkq + 1][lrow] = bPf.y;
        Bs[lkq + 2][lrow] = bPf.z; Bs[lkq + 3][lrow] = bPf.w;
        __syncthreads();

        int kn = k0 + 8;
        if (kn < K) {
            if (MODE == 1) {
                aPf = *reinterpret_cast<const float4*>(
                    &A_or_x[(size_t)blockIdx.y * Hh * Bz + (size_t)(kn + arow) * Bz + acol]);
            } else {
                int m = m0 + lrow;
                int tt = m >> 7, b = m & 127;
#pragma unroll
                for (int i = 0; i < 4; i++)
                    aPfS[i] = A_or_x[(size_t)b * (INZ * Tt) + (size_t)(kn + lkq + i) * Tt + tt];
            }
            bPf = *reinterpret_cast<const float4*>(&W[(size_t)(n0 + lrow) * K + kn + lkq]);
        }

#pragma unroll
        for (int kk = 0; kk < 8; kk++) {
            float a[8];
            *reinterpret_cast<float4*>(&a[0]) = *reinterpret_cast<const float4*>(&As[kk][tyy * 8]);
            *reinterpret_cast<float4*>(&a[4]) = *reinterpret_cast<const float4*>(&As[kk][tyy * 8 + 4]);
            ulonglong2 bp01 = *reinterpret_cast<const ulonglong2*>(&Bs[kk][txx * 8]);
            ulonglong2 bp23 = *reinterpret_cast<const ulonglong2*>(&Bs[kk][txx * 8 + 4]);
            u64 bp[4] = {bp01.x, bp01.y, bp23.x, bp23.y};
#pragma unroll
            for (int i = 0; i < 8; i++) {
                u64 as = pack2(a[i], a[i]);
#pragma unroll
                for (int j = 0; j < 4; j++)
                    acc[i][j] = fma2(as, bp[j], acc[i][j]);
            }
        }
        __syncthreads();
    }

#pragma unroll
    for (int i = 0; i < 8; i++) {
        int m = m0 + tyy * 8 + i;
#pragma unroll
        for (int j = 0; j < 4; j++) {
            int n = n0 + txx * 8 + 2 * j;
            float lo, hi; unpack2(acc[i][j], lo, hi);
            float2 v = make_float2(lo + b0v[n] + b1v[n], hi + b0v[n + 1] + b1v[n + 1]);
            *reinterpret_cast<float2*>(&out[(size_t)m * G4 + n]) = v;
        }
    }
}

// ---------------- persistent LSTM (R4 structure + chunk stagger) ----------------
// 128 blocks x 512 threads. Block owns 4 hidx x 4 gates (16 weight rows,
// pre-splatted f32x2 in SMEM). 4 chunks of 128 k-rows, processed in rotated
// order (c + bid) & 3 to smooth the post-barrier L2 burst. Double-buffered
// cp.async, 1 sync/chunk. Monotonic red.release grid barrier between steps.
__global__ void __launch_bounds__(512, 1)
lstm_persistent(const float* __restrict__ xp_all,   // [t][b][2048]
                const float* __restrict__ whh,      // [2048][512]
                const float* __restrict__ c0,       // [b][512]
                float* __restrict__ hbuf0,          // [512][128]
                float* __restrict__ hbuf1,
                float* __restrict__ hs_t,           // [t][512][128]
                int barSel) {
    extern __shared__ char sm_[];
    u64*   ws2 = (u64*)sm_;                               // [512][16] splats, 64KB
    float* hb  = (float*)(sm_ + 65536);                   // [2][128][128] 128KB
    u64*   red = (u64*)(sm_ + 65536 + 131072);            // [3][128][8] 24KB
    float* xs  = (float*)(sm_ + 65536 + 131072 + 24576);  // [512][4] 8KB
    float* cst = (float*)(sm_ + 65536 + 131072 + 24576 + 8192);  // [4][128] 2KB

    const int tid   = threadIdx.x;
    const int g     = tid >> 7;          // k-group 0..3
    const int tid7  = tid & 127;
    const int hh    = tid7 & 3;
    const int bq    = tid7 >> 2;
    const int hidx0 = blockIdx.x * 4;
    const int rot   = blockIdx.x & 3;    // chunk rotation

    // one-time weight load, pre-splatted: ws2[k][wh*4+q] = (w,w)
    for (int r = tid; r < 512 * 16; r += 512) {
        int k = r >> 4, idx = r & 15;
        int wh = idx >> 2, q = idx & 3;
        float w = whh[(size_t)(q * Hh + hidx0 + wh) * Hh + k];
        ws2[r] = pack2(w, w);
    }
    if (tid < 128) {
#pragma unroll
        for (int j = 0; j < 4; j++)
            cst[hh * 128 + bq * 4 + j] = c0[(size_t)(bq * 4 + j) * Hh + hidx0 + hh];
    }
    __syncthreads();

    unsigned* barCnt = &g_barCnt[barSel];
    const unsigned hb_s = (unsigned)__cvta_generic_to_shared(hb);

    // prefetch xp for t=0 (xs index = tid = b*4+q, holds hidx0..hidx0+3)
    float4 xr = *reinterpret_cast<const float4*>(
        &xp_all[(size_t)(tid >> 2) * G4 + (tid & 3) * Hh + hidx0]);

    for (int t = 0; t < Tt; t++) {
        const float* hp = (t & 1) ? hbuf1 : hbuf0;
        float*       hn = (t & 1) ? hbuf0 : hbuf1;

        // issue first (rotated) chunk into slot 0
        {
            unsigned sa = hb_s + tid * 16;
            const char* gp = (const char*)(hp + rot * 16384) + tid * 16;
#pragma unroll
            for (int i = 0; i < 8; i++)
                asm volatile("cp.async.cg.shared.global [%0], [%1], 16;"
                             :: "r"(sa + i * 8192), "l"(gp + i * 8192));
            asm volatile("cp.async.commit_group;" ::: "memory");
        }

        u64 acc[8];
#pragma unroll
        for (int j = 0; j < 8; j++) acc[j] = 0ull;

#pragma unroll
        for (int c = 0; c < 4; c++) {
            asm volatile("cp.async.wait_group 0;" ::: "memory");
            __syncthreads();

            if (c < 3) {
                int can = (c + 1 + rot) & 3;   // next chunk (absolute)
                unsigned sa = hb_s + ((c + 1) & 1) * 65536 + tid * 16;
                const char* gp = (const char*)(hp + can * 16384) + tid * 16;
#pragma unroll
                for (int i = 0; i < 8; i++)
                    asm volatile("cp.async.cg.shared.global [%0], [%1], 16;"
                                 :: "r"(sa + i * 8192), "l"(gp + i * 8192));
                asm volatile("cp.async.commit_group;" ::: "memory");
            }

            const int ca = (c + rot) & 3;      // this chunk (absolute)
            const float* bufk = hb + (c & 1) * 16384 + (size_t)(g * 32) * 128 + bq * 4;
            const u64*   wk   = ws2 + (size_t)(ca * 128 + g * 32) * 16 + hh * 4;
#pragma unroll 16
            for (int kk = 0; kk < 32; kk++) {
                ulonglong2 hpair = *reinterpret_cast<const ulonglong2*>(bufk + (size_t)kk * 128);
                ulonglong2 w01 = *reinterpret_cast<const ulonglong2*>(wk + (size_t)kk * 16);
                ulonglong2 w23 = *reinterpret_cast<const ulonglong2*>(wk + (size_t)kk * 16 + 2);
                acc[0] = fma2(hpair.x, w01.x, acc[0]);
                acc[4] = fma2(hpair.y, w01.x, acc[4]);
                acc[1] = fma2(hpair.x, w01.y, acc[1]);
                acc[5] = fma2(hpair.y, w01.y, acc[5]);
                acc[2] = fma2(hpair.x, w23.x, acc[2]);
                acc[6] = fma2(hpair.y, w23.x, acc[6]);
                acc[3] = fma2(hpair.x, w23.y, acc[3]);
                acc[7] = fma2(hpair.y, w23.y, acc[7]);
            }
        }

        // stage xp + partials
        *reinterpret_cast<float4*>(&xs[tid * 4]) = xr;
        if (g != 0) {
            u64* r = red + (size_t)(g - 1) * 1024 + tid7 * 8;
#pragma unroll
            for (int j = 0; j < 8; j++) r[j] = acc[j];
        }
        __syncthreads();

        if (g == 0) {
            float gate[4][4];   // [q][j]
#pragma unroll
            for (int p = 0; p < 2; p++)
#pragma unroll
                for (int q = 0; q < 4; q++) {
                    u64 s = acc[p * 4 + q];
                    s = add2(s, red[0 * 1024 + tid7 * 8 + p * 4 + q]);
                    s = add2(s, red[1 * 1024 + tid7 * 8 + p * 4 + q]);
                    s = add2(s, red[2 * 1024 + tid7 * 8 + p * 4 + q]);
                    unpack2(s, gate[q][p * 2 + 0], gate[q][p * 2 + 1]);
                }
            float hv[4];
#pragma unroll
            for (int j = 0; j < 4; j++) {
                int b = bq * 4 + j;
                float gi = gate[0][j] + xs[b * 16 + 0 + hh];
                float gf = gate[1][j] + xs[b * 16 + 4 + hh];
                float gg = gate[2][j] + xs[b * 16 + 8 + hh];
                float go = gate[3][j] + xs[b * 16 + 12 + hh];
                float cc = fsig(gf) * cst[hh * 128 + b] + fsig(gi) * ftanh_(gg);
                cst[hh * 128 + b] = cc;
                hv[j] = fsig(go) * ftanh_(cc);
            }
            float4 h4 = make_float4(hv[0], hv[1], hv[2], hv[3]);
            int off = (hidx0 + hh) * 128 + bq * 4;
            *reinterpret_cast<float4*>(&hn[off]) = h4;
            *reinterpret_cast<float4*>(&hs_t[(size_t)t * Hh * Bz + off]) = h4;
        }

        // prefetch next step's xp (independent of h) before the barrier
        if (t + 1 < Tt)
            xr = *reinterpret_cast<const float4*>(
                &xp_all[(size_t)(t + 1) * Bz * G4 +
                        (size_t)(tid >> 2) * G4 + (tid & 3) * Hh + hidx0]);

        if (t + 1 < Tt) {
            __syncthreads();
            if (tid == 0) {
                red_rel_add(barCnt, 1u);
                unsigned target = (unsigned)(NBLK * (t + 1));
                while (ld_acq(barCnt) < target) {}
            }
            __syncthreads();
        }
    }
}

// ---------------- encoder output transpose: out[b][h][t] = hse_t[t][h][b] ----------------
__global__ void __launch_bounds__(256)
enc_transpose(const float* __restrict__ hs_t, float* __restrict__ out) {
    __shared__ float tile[32][33];
    int t0 = blockIdx.x * 32, b0 = blockIdx.y * 32, h = blockIdx.z;
    int tx = threadIdx.x & 31, ty = threadIdx.x >> 5;
#pragma unroll
    for (int i = ty; i < 32; i += 8)
        tile[i][tx] = hs_t[(size_t)(t0 + i) * (Hh * Bz) + (size_t)h * Bz + b0 + tx];
    __syncthreads();
#pragma unroll
    for (int i = ty; i < 32; i += 8)
        out[(size_t)(b0 + i) * (Hh * Tt) + (size_t)h * Tt + t0 + tx] = tile[tx][i];
}

// ---------------- FC partial GEMM (f32x2, k-split over t) ----------------
__global__ void __launch_bounds__(256)
fc_partial(const float* __restrict__ hsd_t, const float* __restrict__ Wfc) {
    const int t  = blockIdx.y;
    const int o0 = blockIdx.x * 128;
    const int tid = threadIdx.x;
    const int txx = tid & 15;
    const int tyy = tid >> 4;
    const int lrow = tid >> 1;
    const int lkq  = (tid & 1) * 4;
    const int arow = tid >> 5;
    const int acol = (tid & 31) * 4;

    __shared__ __align__(16) float As[8][128];
    __shared__ __align__(16) float Bs[8][128];

    u64 acc[8][4];
#pragma unroll
    for (int i = 0; i < 8; i++)
#pragma unroll
        for (int j = 0; j < 4; j++) acc[i][j] = 0ull;

    const float* Abase = hsd_t + (size_t)t * (Hh * Bz);

    for (int h0 = 0; h0 < Hh; h0 += 8) {
        *reinterpret_cast<float4*>(&As[arow][acol]) =
            *reinterpret_cast<const float4*>(&Abase[(size_t)(h0 + arow) * Bz + acol]);
#pragma unroll
        for (int i = 0; i < 4; i++)
            Bs[lkq + i][lrow] = Wfc[(size_t)(o0 + lrow) * (Hh * Tt) + (size_t)(h0 + lkq + i) * Tt + t];
        __syncthreads();
#pragma unroll
        for (int kk = 0; kk < 8; kk++) {
            float a[8];
            *reinterpret_cast<float4*>(&a[0]) = *reinterpret_cast<const float4*>(&As[kk][tyy * 8]);
            *reinterpret_cast<float4*>(&a[4]) = *reinterpret_cast<const float4*>(&As[kk][tyy * 8 + 4]);
            ulonglong2 bp01 = *reinterpret_cast<const ulonglong2*>(&Bs[kk][txx * 8]);
            ulonglong2 bp23 = *reinterpret_cast<const ulonglong2*>(&Bs[kk][txx * 8 + 4]);
            u64 bp[4] = {bp01.x, bp01.y, bp23.x, bp23.y};
#pragma unroll
            for (int i = 0; i < 8; i++) {
                u64 as = pack2(a[i], a[i]);
#pragma unroll
                for (int j = 0; j < 4; j++)
                    acc[i][j] = fma2(as, bp[j], acc[i][j]);
            }
        }
        __syncthreads();
    }

    float* part = g_fcp + (size_t)t * (Bz * OUTL);
#pragma unroll
    for (int i = 0; i < 8; i++) {
        int b = tyy * 8 + i;
#pragma unroll
        for (int j = 0; j < 4; j++) {
            float lo, hi; unpack2(acc[i][j], lo, hi);
            *reinterpret_cast<float2*>(&part[(size_t)b * OUTL + o0 + txx * 8 + 2 * j]) =
                make_float2(lo, hi);
        }
    }
}

__global__ void fc_reduce(const float* __restrict__ bfc, float* __restrict__ decoded) {
    int i = blockIdx.x * blockDim.x + threadIdx.x;
    if (i >= Bz * OUTL) return;
    float s = bfc[i & (OUTL - 1)];
    for (int t = 0; t < Tt; t++) s += g_fcp[(size_t)t * (Bz * OUTL) + i];
    decoded[i] = s;
}

// ---------------- launch ----------------
extern "C" void kernel_launch(void* const* d_in, const int* in_sizes, int n_in,
                              void* d_out, int out_size) {
    const float* x     = (const float*)d_in[0];
    const float* h0e   = (const float*)d_in[1];
    const float* c0e   = (const float*)d_in[2];
    const float* Wih_e = (const float*)d_in[3];
    const float* Whh_e = (const float*)d_in[4];
    const float* bih_e = (const float*)d_in[5];
    const float* bhh_e = (const float*)d_in[6];
    const float* h0d   = (const float*)d_in[7];
    const float* c0d   = (const float*)d_in[8];
    const float* Wih_d = (const float*)d_in[9];
    const float* Whh_d = (const float*)d_in[10];
    const float* bih_d = (const float*)d_in[11];
    const float* bhh_d = (const float*)d_in[12];
    const float* Wfc   = (const float*)d_in[13];
    const float* bfc   = (const float*)d_in[14];

    float* out = (float*)d_out;
    float* enc_out = out;
    float* decoded = out + (size_t)Bz * Hh * Tt;

    float *xpe, *xpd, *hse, *hsd, *hA, *hB, *h2A, *h2B;
    cudaGetSymbolAddress((void**)&xpe, g_xpe);
    cudaGetSymbolAddress((void**)&xpd, g_xpd);
    cudaGetSymbolAddress((void**)&hse, g_hse);
    cudaGetSymbolAddress((void**)&hsd, g_hsd);
    cudaGetSymbolAddress((void**)&hA,  g_hA);
    cudaGetSymbolAddress((void**)&hB,  g_hB);
    cudaGetSymbolAddress((void**)&h2A, g_h2A);
    cudaGetSymbolAddress((void**)&h2B, g_h2B);

    const int SMEM = 65536 + 131072 + 24576 + 8192 + 2048;   // 231424
    cudaFuncSetAttribute(lstm_persistent, cudaFuncAttributeMaxDynamicSharedMemorySize, SMEM);

    init_h<<<(Hh * Bz + 255) / 256, 256>>>(h0e, h0d);
    init_bar<<<1, 32>>>();

    inproj_gemm<0><<<dim3(16, 256), 256>>>(x, Wih_e, bih_e, bhh_e, xpe, INZ);

    lstm_persistent<<<NBLK, 512, SMEM>>>(xpe, Whh_e, c0e, hA, hB, hse, 0);

    inproj_gemm<1><<<dim3(16, 256), 256>>>(hse, Wih_d, bih_d, bhh_d, xpd, Hh);

    lstm_persistent<<<NBLK, 512, SMEM>>>(xpd, Whh_d, c0d, h2A, h2B, hsd, 1);

    enc_transpose<<<dim3(Tt / 32, Bz / 32, Hh), 256>>>(hse, enc_out);

    fc_partial<<<dim3(4, Tt), 256>>>(hsd, Wfc);
    fc_reduce<<<(Bz * OUTL + 255) / 256, 256>>>(bfc, decoded);
}